// round 10
// baseline (speedup 1.0000x reference)
#include <cuda_runtime.h>
#include <math.h>

#define B_ 128
#define T_ 1024
#define D_ 128
#define U_ 256
#define M_ 64

// Static device scratch (no cudaMalloc anywhere)
__device__ float g_X[134217728];      // [t][gu(1024)][b(128)] fp32

// ---------------------------------------------------------------------------
// f32x2 packed helpers
// ---------------------------------------------------------------------------
__device__ __forceinline__ void fma2(unsigned long long& d,
                                     unsigned long long a,
                                     unsigned long long b) {
    asm("fma.rn.f32x2 %0, %1, %2, %0;" : "+l"(d) : "l"(a), "l"(b));
}
__device__ __forceinline__ float sum2(unsigned long long v) {
    return __uint_as_float((unsigned)v) + __uint_as_float((unsigned)(v >> 32));
}
__device__ __forceinline__ unsigned long long pk2(float a, float b) {
    unsigned long long r;
    asm("mov.b64 %0, {%1, %2};" : "=l"(r) : "f"(a), "f"(b));
    return r;
}
__device__ __forceinline__ unsigned smu32(const void* p) {
    return (unsigned)__cvta_generic_to_shared(p);
}

// ---- mbarrier primitives ----
__device__ __forceinline__ void mb_init(unsigned mbar, unsigned count) {
    asm volatile("mbarrier.init.shared.b64 [%0], %1;"
                 :: "r"(mbar), "r"(count) : "memory");
}
__device__ __forceinline__ void mb_expect_tx(unsigned mbar, unsigned bytes) {
    asm volatile("mbarrier.arrive.expect_tx.shared.b64 _, [%0], %1;"
                 :: "r"(mbar), "r"(bytes) : "memory");
}
__device__ __forceinline__ void mb_wait(unsigned mbar, unsigned parity) {
    unsigned done;
    asm volatile(
        "{\n\t.reg .pred p;\n\t"
        "mbarrier.try_wait.parity.acquire.cta.shared::cta.b64 p, [%1], %2;\n\t"
        "selp.b32 %0, 1, 0, p;\n\t}"
        : "=r"(done) : "r"(mbar), "r"(parity) : "memory");
    while (!done) {
        asm volatile(
            "{\n\t.reg .pred p;\n\t"
            "mbarrier.try_wait.parity.acquire.cta.shared::cta.b64 p, [%1], %2, 0x989680;\n\t"
            "selp.b32 %0, 1, 0, p;\n\t}"
            : "=r"(done) : "r"(mbar), "r"(parity) : "memory");
    }
}

// ---------------------------------------------------------------------------
// K1: input projections, f32x2. Tile 64 gu x 128 b, K=128. 256 thr, 4x8 micro.
// ---------------------------------------------------------------------------
#define K1_SMEM_BYTES ((128 * 68 + 128 * 130) * 4)
__global__ void __launch_bounds__(256) proj_kernel(
    const float* __restrict__ inp,
    const float* __restrict__ Wi, const float* __restrict__ Wf,
    const float* __restrict__ Wc, const float* __restrict__ Wo,
    const float* __restrict__ bi, const float* __restrict__ bf,
    const float* __restrict__ bc, const float* __restrict__ bo)
{
    extern __shared__ float sm[];
    float* Wsh = sm;               // [d=128][68]
    float* Ish = sm + 128 * 68;    // [b=128][130]

    const int t   = blockIdx.y;
    const int gu0 = blockIdx.x * 64;
    const int tid = threadIdx.x;

    const int g = gu0 >> 8;
    const float* Wg = (g == 0) ? Wi : (g == 1) ? Wf : (g == 2) ? Wc : Wo;
    const float* bv = (g == 0) ? bi : (g == 1) ? bf : (g == 2) ? bc : bo;
    const int u0 = gu0 & 255;

    for (int i = tid; i < 128 * 64; i += 256) {
        int d = i >> 6, j = i & 63;
        Wsh[d * 68 + j] = Wg[d * U_ + u0 + j];
    }
    for (int i = tid; i < 128 * 128; i += 256) {
        int b = i >> 7, d = i & 127;
        Ish[b * 130 + d] = inp[((size_t)b * T_ + t) * D_ + d];
    }
    __syncthreads();

    const int j4 = (tid & 15) * 4;
    const int b8 = (tid >> 4) * 8;

    unsigned long long acc[4][8];
#pragma unroll
    for (int jj = 0; jj < 4; jj++)
#pragma unroll
        for (int bb = 0; bb < 8; bb++) acc[jj][bb] = 0ull;

#pragma unroll 8
    for (int d = 0; d < 128; d += 2) {
        float4 wa = *(const float4*)&Wsh[d * 68 + j4];
        float4 wb = *(const float4*)&Wsh[(d + 1) * 68 + j4];
        unsigned long long w0 = pk2(wa.x, wb.x), w1 = pk2(wa.y, wb.y);
        unsigned long long w2 = pk2(wa.z, wb.z), w3 = pk2(wa.w, wb.w);
#pragma unroll
        for (int bb = 0; bb < 8; bb++) {
            unsigned long long iv =
                *(const unsigned long long*)&Ish[(b8 + bb) * 130 + d];
            fma2(acc[0][bb], w0, iv);
            fma2(acc[1][bb], w1, iv);
            fma2(acc[2][bb], w2, iv);
            fma2(acc[3][bb], w3, iv);
        }
    }

    float* outp = g_X + ((size_t)t * 1024 + gu0) * 128;
#pragma unroll
    for (int jj = 0; jj < 4; jj++) {
        float bb_ = bv[u0 + j4 + jj];
        float r[8];
#pragma unroll
        for (int bb = 0; bb < 8; bb++) r[bb] = sum2(acc[jj][bb]) + bb_;
        *(float4*)&outp[(size_t)(j4 + jj) * 128 + b8] =
            make_float4(r[0], r[1], r[2], r[3]);
        *(float4*)&outp[(size_t)(j4 + jj) * 128 + b8 + 4] =
            make_float4(r[4], r[5], r[6], r[7]);
    }
}

// ---------------------------------------------------------------------------
// K2: persistent recurrence, cluster-8, 640 threads, broadcast-clean GEMV.
// CTA (bg, sl): 8 batch rows x 32-col slice of {Ui,Uf,Uc,Uo,Cmem}.
// Thread map: g = tid>>7 (matrix), q4 = (tid>>5)&3 (K-quarter), c = tid&31.
// One warp = one (g,q4): h loads are FULL-WARP UNIFORM (broadcast, N=1).
// Weights packed 4-consecutive-k per float4 per column.
// Each thread: 1 col x 64 K x 8 b = 256 fma2; zbuf has 4 K-partials.
// h via bulk DSMEM push + slice mbarriers (each thread waits 2 sources).
// ---------------------------------------------------------------------------
#define SMW_F4   10240                       // 5*4*16*32 float4 = 163,840 B
#define SHH_OFF  40960                       // [2][src 8][264] floats
#define SHH_SRC  264                         // 8b x 32k + pad (1056 B, 16B-aligned)
#define SHH_BUF  (8 * SHH_SRC)               // 2112 floats per buffer
#define SHX_OFF  (SHH_OFF + 2 * SHH_BUF)     // 45184: [4][32][9]
#define ZB_OFF   (SHX_OFF + 4 * 32 * 9)      // 46336: [4][5][8][32]
#define HST_OFF  (ZB_OFF + 4 * 5 * 8 * 32)   // 51456: [2][256]
#define MBAR_OFF (HST_OFF + 512)             // 51968: 8 mbarriers
#define R_SMEM_BYTES ((MBAR_OFF + 16) * 4)   // 207,936 B

__global__ void __launch_bounds__(640, 1) __cluster_dims__(8, 1, 1)
recur_kernel(const float* __restrict__ Ui, const float* __restrict__ Uf,
             const float* __restrict__ Uc, const float* __restrict__ Uo,
             const float* __restrict__ Wmem, const float* __restrict__ Umem,
             float* __restrict__ out)
{
    extern __shared__ float sm[];
    float4* wsm4 = (float4*)sm;
    float*  shh  = sm + SHH_OFF;
    float*  shx  = sm + SHX_OFF;
    float*  zb   = sm + ZB_OFF;
    float*  hst  = sm + HST_OFF;

    const int bg   = blockIdx.x >> 3;
    const int sl   = blockIdx.x & 7;
    const int tid  = threadIdx.x;
    const int g    = tid >> 7;               // 0..4  matrix
    const int q4   = (tid >> 5) & 3;         // 0..3  K-quarter
    const int c    = tid & 31;               // column

    const unsigned smb   = smu32(sm);
    const unsigned shh_u = smb + SHH_OFF * 4;
    const unsigned hst_u = smb + HST_OFF * 4;
    const unsigned mb0   = smb + MBAR_OFF * 4;    // mbar[q] = mb0 + q*8
    const unsigned mbA   = mb0 + (unsigned)(2 * q4) * 8;
    const unsigned mbB   = mbA + 8;
    const bool     poster = (g == 0 && c == 0);   // 4 posters, 2 mbars each

    // ---- mbarrier init ----
    if (tid < 8) mb_init(mb0 + tid * 8, 1);
    __syncthreads();

    // per-peer bulk-push addresses (threads 0..7, peer = tid)
    unsigned rd_base = 0, rm_peer = 0;
    if (tid < 8) {
        asm("mapa.shared::cluster.u32 %0, %1, %2;" : "=r"(rd_base)
            : "r"(shh_u + (unsigned)(sl * SHH_SRC * 4)), "r"(tid));
        asm("mapa.shared::cluster.u32 %0, %1, %2;" : "=r"(rm_peer)
            : "r"(mb0 + (unsigned)(sl * 8)), "r"(tid));
    }

    // ---- weights into SMEM, 4-consecutive-k packing ----
    // float4 idx = (((gg*4+qq)*16 + kgrp)*32 + cc)
    //   = { W[k][col], W[k+1][col], W[k+2][col], W[k+3][col] },
    //     k = qq*64 + kgrp*4, col = sl*32 + cc.
    // gg==4 (Cmem = 0.1*Umem@Wmem) computed on the fly.
    for (int idx = tid; idx < SMW_F4; idx += 640) {
        int cc   = idx & 31;
        int kgrp = (idx >> 5) & 15;
        int qq   = (idx >> 9) & 3;
        int gg   = idx >> 11;
        int k    = qq * 64 + kgrp * 4;
        int col  = sl * 32 + cc;
        float4 v;
        if (gg < 4) {
            const float* W = (gg == 0) ? Ui : (gg == 1) ? Uf :
                             (gg == 2) ? Uc : Uo;
            v.x = W[(size_t)k * 256 + col];
            v.y = W[(size_t)(k + 1) * 256 + col];
            v.z = W[(size_t)(k + 2) * 256 + col];
            v.w = W[(size_t)(k + 3) * 256 + col];
        } else {
            float s0 = 0.f, s1 = 0.f, s2 = 0.f, s3 = 0.f;
#pragma unroll 8
            for (int m = 0; m < M_; m++) {
                float w = Wmem[m * U_ + col];
                s0 = fmaf(Umem[k * M_ + m],       w, s0);
                s1 = fmaf(Umem[(k + 1) * M_ + m], w, s1);
                s2 = fmaf(Umem[(k + 2) * M_ + m], w, s2);
                s3 = fmaf(Umem[(k + 3) * M_ + m], w, s3);
            }
            v.x = 0.1f * s0; v.y = 0.1f * s1;
            v.z = 0.1f * s2; v.w = 0.1f * s3;
        }
        wsm4[idx] = v;
    }
    for (int i = tid; i < 2 * SHH_BUF; i += 640) shh[i] = 0.f;

    // gate-thread persistent quantities (tid < 256)
    const int gb   = tid >> 5;
    const int gcc  = tid & 31;
    const int u32_ = (tid >> 3) & 31;
    const int bb_  = tid & 7;
    size_t xoff = ((size_t)(sl * 32 + u32_)) * 128 + bg * 8 + bb_;
    float creg = 0.f, rreg = 0.f;
    float* outp = out + ((size_t)(bg * 8 + gb) * T_) * U_ + sl * 32 + gcc;

    if (tid < 256) {                        // stage x for t = 0
        const float* xp = g_X + xoff;
        shx[(0 * 32 + u32_) * 9 + bb_] = xp[0];
        shx[(1 * 32 + u32_) * 9 + bb_] = xp[32768];
        shx[(2 * 32 + u32_) * 9 + bb_] = xp[65536];
        shx[(3 * 32 + u32_) * 9 + bb_] = xp[98304];
    }
    if (poster) {                           // phase 0 (consumed at t=1)
        mb_expect_tx(mbA, 1024);
        mb_expect_tx(mbB, 1024);
    }
    __syncthreads();
    asm volatile("barrier.cluster.arrive.aligned;" ::: "memory");
    asm volatile("barrier.cluster.wait.aligned;" ::: "memory");

    const float4* wpp  = wsm4 + ((g * 4 + q4) * 16) * 32 + c;
    float*        zrow = zb + (q4 * 5 + g) * 256 + c;

    for (int t = 0; t < T_; t++) {
        const int cur = t & 1;
        const float* hbase = shh + cur * SHH_BUF + (2 * q4) * SHH_SRC;

        // ---- prefetch x_{t+1} into registers (no h dependency) ----
        float xr0, xr1, xr2, xr3;
        const bool pf = (tid < 256) && (t + 1 < T_);
        if (pf) {
            const float* xp = g_X + (size_t)(t + 1) * 131072 + xoff;
            xr0 = xp[0]; xr1 = xp[32768]; xr2 = xp[65536]; xr3 = xp[98304];
        }

        // ---- wait for my TWO source slices of h (phase t-1), repost ----
        if (t > 0) {
            mb_wait(mbA, (unsigned)((t - 1) & 1));
            mb_wait(mbB, (unsigned)((t - 1) & 1));
            if (poster) {
                mb_expect_tx(mbA, 1024);
                mb_expect_tx(mbB, 1024);
            }
        }

        // ---- z = h_prev @ W : 1 col, 64 K, 8 b per thread (f32x2) ----
        // h loads are warp-uniform (broadcast); w loads 512B contiguous.
        unsigned long long a[8];
#pragma unroll
        for (int b = 0; b < 8; b++) a[b] = 0ull;
#pragma unroll
        for (int kg = 0; kg < 16; kg++) {
            ulonglong2 w = *(const ulonglong2*)(wpp + kg * 32);
            const float* hp = hbase + (kg >> 3) * SHH_SRC + (kg & 7) * 4;
#pragma unroll
            for (int b = 0; b < 8; b++) {
                ulonglong2 hh = *(const ulonglong2*)(hp + b * 32);
                fma2(a[b], w.x, hh.x);     // k0,k1
                fma2(a[b], w.y, hh.y);     // k2,k3
            }
        }
#pragma unroll
        for (int b = 0; b < 8; b++) zrow[b * 32] = sum2(a[b]);
        __syncthreads();                      // zbuf complete for gates

        // ---- gates + state + push (tid<256: one (b, col) cell) ----
        if (tid < 256) {
            float zi = 0, zf = 0, zc = 0, zo = 0, zr = 0;
#pragma unroll
            for (int q = 0; q < 4; q++) {
                const float* zq = zb + q * 5 * 256 + gb * 32 + gcc;
                zi += zq[0];
                zf += zq[256];
                zc += zq[512];
                zo += zq[768];
                zr += zq[1024];
            }
            float rn = rreg + zr;
            float pi  = shx[(0 * 32 + gcc) * 9 + gb] + zi + rn;
            float pff = shx[(1 * 32 + gcc) * 9 + gb] + zf;
            float pc  = shx[(2 * 32 + gcc) * 9 + gb] + zc;
            float po  = shx[(3 * 32 + gcc) * 9 + gb] + zo;
            float ig = __fdividef(1.f, 1.f + __expf(-pi));
            float fg = __fdividef(1.f, 1.f + __expf(-pff));
            float ct = __fdividef(2.f, 1.f + __expf(-2.f * pc)) - 1.f;
            float og = __fdividef(1.f, 1.f + __expf(-po));
            float cn = fg * creg + ig * ct;
            float hv = og * (__fdividef(2.f, 1.f + __expf(-2.f * cn)) - 1.f);
            creg = cn;
            rreg = rn;
            hst[cur * 256 + tid] = hv;

            asm volatile("bar.sync 1, 256;" ::: "memory");

            // bulk-push my slice (1KB) to each peer, tx-counted at its mbar
            if (tid < 8 && t + 1 < T_) {
                asm volatile("fence.proxy.async.shared::cta;" ::: "memory");
                unsigned dst = rd_base +
                    (unsigned)(((t + 1) & 1) * SHH_BUF * 4);
                unsigned src = hst_u + (unsigned)(cur * 1024);
                asm volatile(
                    "cp.async.bulk.shared::cluster.shared::cta"
                    ".mbarrier::complete_tx::bytes [%0], [%1], %2, [%3];"
                    :: "r"(dst), "r"(src), "r"(1024u), "r"(rm_peer)
                    : "memory");
            }

            outp[(size_t)t * U_] = hv;       // off the comm critical path

            // commit prefetched x (all gate reads of shx are done: bar 1)
            if (pf) {
                shx[(0 * 32 + u32_) * 9 + bb_] = xr0;
                shx[(1 * 32 + u32_) * 9 + bb_] = xr1;
                shx[(2 * 32 + u32_) * 9 + bb_] = xr2;
                shx[(3 * 32 + u32_) * 9 + bb_] = xr3;
            }
        }
        // non-gate threads loop to next mb_wait; protected by the dataflow:
        // phase t completes only after ALL 8 sources' pushes (incl. own CTA,
        // which happens after bar 1 => after all zbuf/shx reads of step t).
    }

    // no CTA may exit while peers' bulk copies into its SMEM are in flight
    asm volatile("barrier.cluster.arrive.aligned;" ::: "memory");
    asm volatile("barrier.cluster.wait.aligned;" ::: "memory");
}

// ---------------------------------------------------------------------------
// Launcher: capture-legal (exactly 2 kernel launches, default stream)
// ---------------------------------------------------------------------------
extern "C" void kernel_launch(void* const* d_in, const int* in_sizes, int n_in,
                              void* d_out, int out_size)
{
    const float* inp  = (const float*)d_in[0];
    const float* Wi   = (const float*)d_in[1];
    const float* Wf   = (const float*)d_in[2];
    const float* Wc   = (const float*)d_in[3];
    const float* Wo   = (const float*)d_in[4];
    const float* Uig  = (const float*)d_in[5];
    const float* Ufg  = (const float*)d_in[6];
    const float* Ucg  = (const float*)d_in[7];
    const float* Uog  = (const float*)d_in[8];
    const float* Wmem = (const float*)d_in[9];
    const float* Umem = (const float*)d_in[10];
    const float* bi   = (const float*)d_in[11];
    const float* bf   = (const float*)d_in[12];
    const float* bc   = (const float*)d_in[13];
    const float* bo   = (const float*)d_in[14];
    float* out = (float*)d_out;

    cudaFuncSetAttribute(proj_kernel,
                         cudaFuncAttributeMaxDynamicSharedMemorySize,
                         K1_SMEM_BYTES);
    dim3 pg(16, 1024);
    proj_kernel<<<pg, 256, K1_SMEM_BYTES, 0>>>(inp, Wi, Wf, Wc, Wo,
                                               bi, bf, bc, bo);

    cudaFuncSetAttribute(recur_kernel,
                         cudaFuncAttributeMaxDynamicSharedMemorySize,
                         R_SMEM_BYTES);
    recur_kernel<<<128, 640, R_SMEM_BYTES, 0>>>(Uig, Ufg, Ucg, Uog,
                                                Wmem, Umem, out);
}

// round 11
// speedup vs baseline: 1.7813x; 1.7813x over previous
#include <cuda_runtime.h>
#include <math.h>

#define B_ 128
#define T_ 1024
#define D_ 128
#define U_ 256
#define M_ 64

// Static device scratch (no cudaMalloc anywhere)
// Layout: [t][bg(16)][sl(8)][g(4)][b(8)][c(32)]  (CTA-contiguous blocks)
__device__ float g_X[134217728];

// ---------------------------------------------------------------------------
// f32x2 packed helpers
// ---------------------------------------------------------------------------
__device__ __forceinline__ void fma2(unsigned long long& d,
                                     unsigned long long a,
                                     unsigned long long b) {
    asm("fma.rn.f32x2 %0, %1, %2, %0;" : "+l"(d) : "l"(a), "l"(b));
}
__device__ __forceinline__ float sum2(unsigned long long v) {
    return __uint_as_float((unsigned)v) + __uint_as_float((unsigned)(v >> 32));
}
__device__ __forceinline__ unsigned long long pk2(float a, float b) {
    unsigned long long r;
    asm("mov.b64 %0, {%1, %2};" : "=l"(r) : "f"(a), "f"(b));
    return r;
}
__device__ __forceinline__ unsigned smu32(const void* p) {
    return (unsigned)__cvta_generic_to_shared(p);
}

// ---- mbarrier primitives ----
__device__ __forceinline__ void mb_init(unsigned mbar, unsigned count) {
    asm volatile("mbarrier.init.shared.b64 [%0], %1;"
                 :: "r"(mbar), "r"(count) : "memory");
}
__device__ __forceinline__ void mb_expect_tx(unsigned mbar, unsigned bytes) {
    asm volatile("mbarrier.arrive.expect_tx.shared.b64 _, [%0], %1;"
                 :: "r"(mbar), "r"(bytes) : "memory");
}
__device__ __forceinline__ void mb_wait(unsigned mbar, unsigned parity) {
    unsigned done;
    asm volatile(
        "{\n\t.reg .pred p;\n\t"
        "mbarrier.try_wait.parity.acquire.cta.shared::cta.b64 p, [%1], %2;\n\t"
        "selp.b32 %0, 1, 0, p;\n\t}"
        : "=r"(done) : "r"(mbar), "r"(parity) : "memory");
    while (!done) {
        asm volatile(
            "{\n\t.reg .pred p;\n\t"
            "mbarrier.try_wait.parity.acquire.cta.shared::cta.b64 p, [%1], %2, 0x989680;\n\t"
            "selp.b32 %0, 1, 0, p;\n\t}"
            : "=r"(done) : "r"(mbar), "r"(parity) : "memory");
    }
}

// ---------------------------------------------------------------------------
// K1: input projections, f32x2. Tile 64 gu x 128 b, K=128. 256 thr, 4x8 micro.
// Stores into the CTA-contiguous g_X layout.
// ---------------------------------------------------------------------------
#define K1_SMEM_BYTES ((128 * 68 + 128 * 130) * 4)
__global__ void __launch_bounds__(256) proj_kernel(
    const float* __restrict__ inp,
    const float* __restrict__ Wi, const float* __restrict__ Wf,
    const float* __restrict__ Wc, const float* __restrict__ Wo,
    const float* __restrict__ bi, const float* __restrict__ bf,
    const float* __restrict__ bc, const float* __restrict__ bo)
{
    extern __shared__ float sm[];
    float* Wsh = sm;               // [d=128][68]
    float* Ish = sm + 128 * 68;    // [b=128][130]

    const int t   = blockIdx.y;
    const int gu0 = blockIdx.x * 64;
    const int tid = threadIdx.x;

    const int g = gu0 >> 8;
    const float* Wg = (g == 0) ? Wi : (g == 1) ? Wf : (g == 2) ? Wc : Wo;
    const float* bv = (g == 0) ? bi : (g == 1) ? bf : (g == 2) ? bc : bo;
    const int u0 = gu0 & 255;

    for (int i = tid; i < 128 * 64; i += 256) {
        int d = i >> 6, j = i & 63;
        Wsh[d * 68 + j] = Wg[d * U_ + u0 + j];
    }
    for (int i = tid; i < 128 * 128; i += 256) {
        int b = i >> 7, d = i & 127;
        Ish[b * 130 + d] = inp[((size_t)b * T_ + t) * D_ + d];
    }
    __syncthreads();

    const int j4 = (tid & 15) * 4;
    const int b8 = (tid >> 4) * 8;

    unsigned long long acc[4][8];
#pragma unroll
    for (int jj = 0; jj < 4; jj++)
#pragma unroll
        for (int bb = 0; bb < 8; bb++) acc[jj][bb] = 0ull;

#pragma unroll 8
    for (int d = 0; d < 128; d += 2) {
        float4 wa = *(const float4*)&Wsh[d * 68 + j4];
        float4 wb = *(const float4*)&Wsh[(d + 1) * 68 + j4];
        unsigned long long w0 = pk2(wa.x, wb.x), w1 = pk2(wa.y, wb.y);
        unsigned long long w2 = pk2(wa.z, wb.z), w3 = pk2(wa.w, wb.w);
#pragma unroll
        for (int bb = 0; bb < 8; bb++) {
            unsigned long long iv =
                *(const unsigned long long*)&Ish[(b8 + bb) * 130 + d];
            fma2(acc[0][bb], w0, iv);
            fma2(acc[1][bb], w1, iv);
            fma2(acc[2][bb], w2, iv);
            fma2(acc[3][bb], w3, iv);
        }
    }

    // store: [t][bg][sl][g][b][c], float4 over 4 consecutive cols per b
    const int u   = u0 + j4;
    const int slo = u >> 5;
    const int co  = u & 31;
    float* outp = g_X + (size_t)t * 131072 + (size_t)(b8 >> 3) * 8192 +
                  slo * 1024 + g * 256 + co;
    const float bv0 = bv[u0 + j4 + 0], bv1 = bv[u0 + j4 + 1];
    const float bv2 = bv[u0 + j4 + 2], bv3 = bv[u0 + j4 + 3];
#pragma unroll
    for (int bb = 0; bb < 8; bb++) {
        float4 v = make_float4(sum2(acc[0][bb]) + bv0,
                               sum2(acc[1][bb]) + bv1,
                               sum2(acc[2][bb]) + bv2,
                               sum2(acc[3][bb]) + bv3);
        *(float4*)(outp + bb * 32) = v;
    }
}

// ---------------------------------------------------------------------------
// K2: persistent recurrence, cluster-8, 640 threads, bulk DSMEM exchange.
// R8 core (GEMV 2 cols x 32 K x 8 b per thread, per-slice mbar dataflow),
// plus: x held in gate-thread registers (no shx), dedicated pusher warp 8.
// ---------------------------------------------------------------------------
#define SMW_F4   10240                       // 163,840 B weights
#define SHH_OFF  40960                       // [2][src 8][264] floats
#define SHH_SRC  264
#define SHH_BUF  (8 * SHH_SRC)               // 2112 floats per buffer
#define ZB_OFF   (SHH_OFF + 2 * SHH_BUF)     // 45184: [8][5][8][32]
#define HST_OFF  (ZB_OFF + 8 * 5 * 8 * 32)   // 55424: [2][256]
#define MBAR_OFF (HST_OFF + 512)             // 55936: 8 mbarriers
#define R_SMEM_BYTES ((MBAR_OFF + 16) * 4)   // 223,808 B

__global__ void __launch_bounds__(640, 1) __cluster_dims__(8, 1, 1)
recur_kernel(const float* __restrict__ Ui, const float* __restrict__ Uf,
             const float* __restrict__ Uc, const float* __restrict__ Uo,
             const float* __restrict__ Wmem, const float* __restrict__ Umem,
             float* __restrict__ out)
{
    extern __shared__ float sm[];
    float4* wsm4 = (float4*)sm;
    float*  shh  = sm + SHH_OFF;
    float*  zb   = sm + ZB_OFF;
    float*  hst  = sm + HST_OFF;

    const int bg   = blockIdx.x >> 3;
    const int sl   = blockIdx.x & 7;
    const int tid  = threadIdx.x;
    const int g    = tid >> 7;               // 0..4  matrix
    const int kq8  = (tid >> 4) & 7;         // 0..7  K-eighth == source slice
    const int cp   = tid & 15;               // column pair

    const unsigned smb   = smu32(sm);
    const unsigned shh_u = smb + SHH_OFF * 4;
    const unsigned hst_u = smb + HST_OFF * 4;
    const unsigned mb0   = smb + MBAR_OFF * 4;    // mbar[q] = mb0 + q*8
    const unsigned my_mb = mb0 + (unsigned)kq8 * 8;
    const bool     poster = (g == 0 && cp == 0);

    // ---- mbarrier init ----
    if (tid < 8) mb_init(mb0 + tid * 8, 1);
    __syncthreads();

    // pusher warp 8 (tid 256..287): lanes 0..7 own one peer each
    unsigned rd_base = 0, rm_peer = 0;
    if (tid >= 256 && tid < 264) {
        const int peer = tid - 256;
        asm("mapa.shared::cluster.u32 %0, %1, %2;" : "=r"(rd_base)
            : "r"(shh_u + (unsigned)(sl * SHH_SRC * 4)), "r"(peer));
        asm("mapa.shared::cluster.u32 %0, %1, %2;" : "=r"(rm_peer)
            : "r"(mb0 + (unsigned)(sl * 8)), "r"(peer));
    }

    // ---- weights into SMEM, f32x2-paired layout (same as R8) ----
    for (int idx = tid; idx < SMW_F4; idx += 640) {
        int lcp = idx & 15;
        int p   = (idx >> 4) & 1;
        int j   = (idx >> 5) & 7;
        int q8  = (idx >> 8) & 7;
        int gg  = idx >> 11;
        int k   = q8 * 32 + j * 4 + 2 * p;
        int col = sl * 32 + lcp * 2;
        float4 v;
        if (gg < 4) {
            const float* W = (gg == 0) ? Ui : (gg == 1) ? Uf :
                             (gg == 2) ? Uc : Uo;
            v.x = W[(size_t)k * 256 + col];
            v.y = W[(size_t)(k + 1) * 256 + col];
            v.z = W[(size_t)k * 256 + col + 1];
            v.w = W[(size_t)(k + 1) * 256 + col + 1];
        } else {
            float s00 = 0.f, s10 = 0.f, s01 = 0.f, s11 = 0.f;
#pragma unroll 8
            for (int m = 0; m < M_; m++) {
                float u0 = Umem[k * M_ + m];
                float u1 = Umem[(k + 1) * M_ + m];
                float w0 = Wmem[m * U_ + col];
                float w1 = Wmem[m * U_ + col + 1];
                s00 = fmaf(u0, w0, s00); s10 = fmaf(u1, w0, s10);
                s01 = fmaf(u0, w1, s01); s11 = fmaf(u1, w1, s11);
            }
            v.x = 0.1f * s00; v.y = 0.1f * s10;
            v.z = 0.1f * s01; v.w = 0.1f * s11;
        }
        wsm4[idx] = v;
    }
    for (int i = tid; i < 2 * SHH_BUF; i += 640) shh[i] = 0.f;

    // gate-thread persistent quantities (tid < 256)
    const int gb  = tid >> 5;
    const int gcc = tid & 31;
    const float* xbase = g_X + (size_t)bg * 8192 + sl * 1024 + gb * 32 + gcc;
    float creg = 0.f, rreg = 0.f;
    float xc0 = 0.f, xc1 = 0.f, xc2 = 0.f, xc3 = 0.f;
    float* outp = out + ((size_t)(bg * 8 + gb) * T_) * U_ + sl * 32 + gcc;

    if (tid < 256) {                        // x for t = 0 into registers
        xc0 = xbase[0];
        xc1 = xbase[256];
        xc2 = xbase[512];
        xc3 = xbase[768];
    }
    if (poster) mb_expect_tx(my_mb, 1024);   // phase 0 (consumed at t=1)
    __syncthreads();
    asm volatile("barrier.cluster.arrive.aligned;" ::: "memory");
    asm volatile("barrier.cluster.wait.aligned;" ::: "memory");

    const float4* wp   = wsm4 + (g * 8 + kq8) * 256 + cp;
    float*        zrow = zb + (kq8 * 5 + g) * 256 + cp * 2;

    for (int t = 0; t < T_; t++) {
        const int cur = t & 1;
        const float* hsrc = shh + cur * SHH_BUF + kq8 * SHH_SRC;

        // ---- prefetch x_{t+1} into registers (no h dependency) ----
        float xr0, xr1, xr2, xr3;
        const bool pf = (tid < 256) && (t + 1 < T_);
        if (pf) {
            const float* xp = xbase + (size_t)(t + 1) * 131072;
            xr0 = xp[0]; xr1 = xp[256]; xr2 = xp[512]; xr3 = xp[768];
        }

        // ---- wait for my source slice of h (phase t-1), repost expect ----
        if (t > 0) {
            mb_wait(my_mb, (unsigned)((t - 1) & 1));
            if (poster) mb_expect_tx(my_mb, 1024);
        }

        // ---- z = h_prev @ W : 2 cols, 32 K, 8 b per thread (f32x2) ----
        unsigned long long a0[8], a1[8];
#pragma unroll
        for (int b = 0; b < 8; b++) { a0[b] = 0ull; a1[b] = 0ull; }
#pragma unroll
        for (int j = 0; j < 8; j++) {
            ulonglong2 wa = *(const ulonglong2*)(wp + j * 32);
            ulonglong2 wb = *(const ulonglong2*)(wp + j * 32 + 16);
#pragma unroll
            for (int b = 0; b < 8; b++) {
                ulonglong2 hh =
                    *(const ulonglong2*)(hsrc + b * 32 + j * 4);
                fma2(a0[b], wa.x, hh.x); fma2(a1[b], wa.y, hh.x);
                fma2(a0[b], wb.x, hh.y); fma2(a1[b], wb.y, hh.y);
            }
        }
#pragma unroll
        for (int b = 0; b < 8; b++) {
            float2 z2 = make_float2(sum2(a0[b]), sum2(a1[b]));
            *(float2*)(zrow + b * 32) = z2;
        }
        __syncthreads();                      // zbuf complete

        // ---- gates + state (tid<256) ; pusher warp (256..287) parks ----
        if (tid < 256) {
            float zi = 0, zf = 0, zc = 0, zo = 0, zr = 0;
#pragma unroll
            for (int q = 0; q < 8; q++) {
                const float* zq = zb + q * 5 * 256 + gb * 32 + gcc;
                zi += zq[0];
                zf += zq[256];
                zc += zq[512];
                zo += zq[768];
                zr += zq[1024];
            }
            float rn = rreg + zr;
            float pi  = xc0 + zi + rn;
            float pff = xc1 + zf;
            float pc  = xc2 + zc;
            float po  = xc3 + zo;
            float ig = __fdividef(1.f, 1.f + __expf(-pi));
            float fg = __fdividef(1.f, 1.f + __expf(-pff));
            float ct = __fdividef(2.f, 1.f + __expf(-2.f * pc)) - 1.f;
            float og = __fdividef(1.f, 1.f + __expf(-po));
            float cn = fg * creg + ig * ct;
            float hv = og * (__fdividef(2.f, 1.f + __expf(-2.f * cn)) - 1.f);
            creg = cn;
            rreg = rn;
            hst[cur * 256 + tid] = hv;
            if (pf) { xc0 = xr0; xc1 = xr1; xc2 = xr2; xc3 = xr3; }

            asm volatile("bar.sync 1, 288;" ::: "memory");

            outp[(size_t)t * U_] = hv;        // off the push critical path
        } else if (tid < 288) {
            // pusher warp: wait for gates' hst, then fire 8 bulk copies
            asm volatile("bar.sync 1, 288;" ::: "memory");
            if (tid < 264 && t + 1 < T_) {
                asm volatile("fence.proxy.async.shared::cta;" ::: "memory");
                unsigned dst = rd_base +
                    (unsigned)(((t + 1) & 1) * SHH_BUF * 4);
                unsigned src = hst_u + (unsigned)(cur * 1024);
                asm volatile(
                    "cp.async.bulk.shared::cluster.shared::cta"
                    ".mbarrier::complete_tx::bytes [%0], [%1], %2, [%3];"
                    :: "r"(dst), "r"(src), "r"(1024u), "r"(rm_peer)
                    : "memory");
            }
        }
        // threads >= 288 loop straight to next mb_wait; protected by the
        // dataflow (phase t completes only after ALL 8 sources' pushes,
        // incl. own CTA's, which happens after bar 1 => after all zbuf
        // reads of step t).
    }

    // no CTA may exit while peers' bulk copies into its SMEM are in flight
    asm volatile("barrier.cluster.arrive.aligned;" ::: "memory");
    asm volatile("barrier.cluster.wait.aligned;" ::: "memory");
}

// ---------------------------------------------------------------------------
// Launcher: capture-legal (exactly 2 kernel launches, default stream)
// ---------------------------------------------------------------------------
extern "C" void kernel_launch(void* const* d_in, const int* in_sizes, int n_in,
                              void* d_out, int out_size)
{
    const float* inp  = (const float*)d_in[0];
    const float* Wi   = (const float*)d_in[1];
    const float* Wf   = (const float*)d_in[2];
    const float* Wc   = (const float*)d_in[3];
    const float* Wo   = (const float*)d_in[4];
    const float* Uig  = (const float*)d_in[5];
    const float* Ufg  = (const float*)d_in[6];
    const float* Ucg  = (const float*)d_in[7];
    const float* Uog  = (const float*)d_in[8];
    const float* Wmem = (const float*)d_in[9];
    const float* Umem = (const float*)d_in[10];
    const float* bi   = (const float*)d_in[11];
    const float* bf   = (const float*)d_in[12];
    const float* bc   = (const float*)d_in[13];
    const float* bo   = (const float*)d_in[14];
    float* out = (float*)d_out;

    cudaFuncSetAttribute(proj_kernel,
                         cudaFuncAttributeMaxDynamicSharedMemorySize,
                         K1_SMEM_BYTES);
    dim3 pg(16, 1024);
    proj_kernel<<<pg, 256, K1_SMEM_BYTES, 0>>>(inp, Wi, Wf, Wc, Wo,
                                               bi, bf, bc, bo);

    cudaFuncSetAttribute(recur_kernel,
                         cudaFuncAttributeMaxDynamicSharedMemorySize,
                         R_SMEM_BYTES);
    recur_kernel<<<128, 640, R_SMEM_BYTES, 0>>>(Uig, Ufg, Ucg, Uog,
                                                Wmem, Umem, out);
}